// round 3
// baseline (speedup 1.0000x reference)
#include <cuda_runtime.h>

// Problem constants
#define BB 256
#define TT 2048
// gates = 4*43 = 172, hidden = 43
// Layer1 combined input dim J1 = 52: ext [0,8) (folded proj), h [8,51), pad 51
// Layer2 combined input dim J2 = 132: ext [0,88) (86+2 pad), h [88,131), pad 131

__device__ __align__(16) float g_W1[2 * 52 * 172];
__device__ __align__(16) float g_b1[2 * 172];
__device__ __align__(16) float g_W2[2 * 132 * 172];
__device__ __align__(16) float g_b2[2 * 172];
__device__ __align__(16) float g_y1[(size_t)BB * TT * 86];
__device__ __align__(16) float g_y2[(size_t)BB * TT * 86];

struct PrepArgs {
    const float* w_proj;   // [43,8]
    const float* b_proj;   // [43]
    const float* wih[4];   // 1f,1b,2f,2b
    const float* whh[4];
    const float* bih[4];
    const float* bhh[4];
};

// Repack all weights into j-major float4-packed layout:
//   W[dir][(j>>2)*172 + r][j&3]
// Layer1 input weights folded with the projection: Weff = w_ih1 @ w_proj.
__global__ void prep_kernel(PrepArgs A) {
    int id = blockIdx.x * blockDim.x + threadIdx.x;
    int NT = gridDim.x * blockDim.x;

    // ---- Layer-1 weights (2 dirs x 52 x 172) ----
    for (int i = id; i < 2 * 52 * 172; i += NT) {
        int dir = i / (52 * 172);
        int rem = i - dir * (52 * 172);
        int j = rem / 172, r = rem % 172;
        float v = 0.f;
        if (j < 8) {
            float s = 0.f;
            for (int k = 0; k < 43; ++k)
                s += A.wih[dir][r * 43 + k] * A.w_proj[k * 8 + j];
            v = s;
        } else if (j - 8 < 43) {
            v = A.whh[dir][r * 43 + (j - 8)];
        }
        g_W1[dir * (52 * 172) + ((j >> 2) * 172 + r) * 4 + (j & 3)] = v;
    }
    // Layer-1 effective bias: w_ih1 @ b_proj + b_ih + b_hh
    for (int i = id; i < 2 * 172; i += NT) {
        int dir = i / 172, r = i % 172;
        float s = A.bih[dir][r] + A.bhh[dir][r];
        for (int k = 0; k < 43; ++k)
            s += A.wih[dir][r * 43 + k] * A.b_proj[k];
        g_b1[i] = s;
    }

    // ---- Layer-2 weights (2 dirs x 132 x 172), same j-major layout ----
    for (int i = id; i < 2 * 132 * 172; i += NT) {
        int dir = i / (132 * 172);
        int rem = i - dir * (132 * 172);
        int j = rem / 172, r = rem % 172;
        int di = 2 + dir;
        float v = 0.f;
        if (j < 88) {
            if (j < 86) v = A.wih[di][r * 86 + j];
        } else if (j - 88 < 43) {
            v = A.whh[di][r * 43 + (j - 88)];
        }
        g_W2[dir * (132 * 172) + ((j >> 2) * 172 + r) * 4 + (j & 3)] = v;
    }
    for (int i = id; i < 2 * 172; i += NT) {
        int dir = i / 172, r = i % 172;
        g_b2[i] = A.bih[2 + dir][r] + A.bhh[2 + dir][r];
    }
}

__device__ __forceinline__ float fsig(float x) {
    return __fdividef(1.f, 1.f + __expf(-x));
}
__device__ __forceinline__ float ftanh_(float x) {
    return 2.f * __fdividef(1.f, 1.f + __expf(-2.f * x)) - 1.f;
}

// ---------------- Layer 1: smem weights (37.5 KB < 48 KB) ----------------
// One block = one batch-pair x one direction. 192 threads.
// Threads 0..171 each compute one gate row for BOTH batch elements.
__global__ __launch_bounds__(192) void lstm1_kernel(const float* __restrict__ x_in) {
    extern __shared__ __align__(16) float sm[];
    const int J = 52, HOFF = 8, INW = 8;
    float* sW = sm;                 // J*172 (float4-packed j-major)
    float* sV = sm + J * 172;       // 2*J : v[j] interleaved {b0,b1}
    float* sG = sV + 2 * J;         // 2*172 : gates interleaved

    const int tid = threadIdx.x;
    const int pair = blockIdx.x >> 1;
    const int dir = blockIdx.x & 1;
    const int b0 = pair * 2, b1 = b0 + 1;

    const float* gW = g_W1 + dir * (J * 172);
    const float* gB = g_b1 + dir * 172;

    for (int i = tid; i < (J * 172) / 4; i += 192)
        ((float4*)sW)[i] = ((const float4*)gW)[i];
    for (int i = tid; i < 2 * J; i += 192) sV[i] = 0.f;

    const float bias = (tid < 172) ? gB[tid] : 0.f;
    float c = 0.f;

    const float* in0 = x_in + (size_t)b0 * TT * INW;
    const float* in1 = x_in + (size_t)b1 * TT * INW;
    float* out0 = g_y1 + (size_t)b0 * TT * 86 + dir * 43;
    float* out1 = g_y1 + (size_t)b1 * TT * 86 + dir * 43;

    const int jmy = tid >> 1;
    const int bbit = tid & 1;
    const float* inme = bbit ? in1 : in0;

    float rin = 0.f;
    if (tid < 2 * INW) {
        int t0 = dir ? (TT - 1) : 0;
        rin = inme[(size_t)t0 * INW + jmy];
    }
    __syncthreads();

    for (int step = 0; step < TT; ++step) {
        const int t = dir ? (TT - 1 - step) : step;

        if (tid < 2 * INW) sV[tid] = rin;
        float rnext = 0.f;
        if (step + 1 < TT && tid < 2 * INW) {
            int tn = dir ? (TT - 2 - step) : (step + 1);
            rnext = inme[(size_t)tn * INW + jmy];
        }
        __syncthreads();  // A: input + h ready

        if (tid < 172) {
            float a00 = bias, a01 = 0.f;
            float a10 = bias, a11 = 0.f;
            const float4* w4 = (const float4*)sW;
            const float4* v4 = (const float4*)sV;
#pragma unroll
            for (int q = 0; q < J / 4; ++q) {
                float4 w = w4[q * 172 + tid];
                float4 va = v4[2 * q + 0];  // j=4q,4q+1 (b0,b1 interleaved)
                float4 vb = v4[2 * q + 1];  // j=4q+2,4q+3
                a00 = fmaf(w.x, va.x, a00);
                a10 = fmaf(w.x, va.y, a10);
                a01 = fmaf(w.y, va.z, a01);
                a11 = fmaf(w.y, va.w, a11);
                a00 = fmaf(w.z, vb.x, a00);
                a10 = fmaf(w.z, vb.y, a10);
                a01 = fmaf(w.w, vb.z, a01);
                a11 = fmaf(w.w, vb.w, a11);
            }
            float z0 = a00 + a01;
            float z1 = a10 + a11;
            bool isg = (tid >= 86) && (tid < 129);
            sG[2 * tid + 0] = isg ? ftanh_(z0) : fsig(z0);
            sG[2 * tid + 1] = isg ? ftanh_(z1) : fsig(z1);
        }
        __syncthreads();  // B: gates ready

        if (tid < 86) {
            int r = jmy;
            float iv = sG[2 * r + bbit];
            float fv = sG[2 * (43 + r) + bbit];
            float gv = sG[2 * (86 + r) + bbit];
            float ov = sG[2 * (129 + r) + bbit];
            c = fv * c + iv * gv;
            float h = ov * ftanh_(c);
            sV[2 * (HOFF + r) + bbit] = h;
            (bbit ? out1 : out0)[(size_t)t * 86 + r] = h;
        }
        rin = rnext;
    }
}

// ---------------- Layer 2: structural clone of layer 1 ----------------
// Identical staging/compute/cell logic; weights streamed from global
// (L1-resident: 91 KB/dir, both dirs fit in 228 KB L1).
__global__ __launch_bounds__(192, 2) void lstm2_kernel() {
    const int J = 132, HOFF = 88, INW = 86;
    __shared__ __align__(16) float sV[2 * 132];
    __shared__ __align__(16) float sG[2 * 172];

    const int tid = threadIdx.x;
    const int pair = blockIdx.x >> 1;
    const int dir = blockIdx.x & 1;
    const int b0 = pair * 2, b1 = b0 + 1;

    const float4* __restrict__ w4 = (const float4*)(g_W2 + dir * (J * 172));
    const float* gB = g_b2 + dir * 172;

    for (int i = tid; i < 2 * J; i += 192) sV[i] = 0.f;

    const float bias = (tid < 172) ? gB[tid] : 0.f;
    float c = 0.f;

    const float* in0 = g_y1 + (size_t)b0 * TT * 86;
    const float* in1 = g_y1 + (size_t)b1 * TT * 86;
    float* out0 = g_y2 + (size_t)b0 * TT * 86 + dir * 43;
    float* out1 = g_y2 + (size_t)b1 * TT * 86 + dir * 43;

    const int jmy = tid >> 1;
    const int bbit = tid & 1;
    const float* inme = bbit ? in1 : in0;

    float rin = 0.f;
    if (tid < 2 * INW) {
        int t0 = dir ? (TT - 1) : 0;
        rin = inme[(size_t)t0 * INW + jmy];
    }
    __syncthreads();

    for (int step = 0; step < TT; ++step) {
        const int t = dir ? (TT - 1 - step) : step;

        if (tid < 2 * INW) sV[tid] = rin;
        float rnext = 0.f;
        if (step + 1 < TT && tid < 2 * INW) {
            int tn = dir ? (TT - 2 - step) : (step + 1);
            rnext = inme[(size_t)tn * 86 + jmy];
        }
        __syncthreads();  // A: input + h ready

        if (tid < 172) {
            float a00 = bias, a01 = 0.f;
            float a10 = bias, a11 = 0.f;
            const float4* v4 = (const float4*)sV;
#pragma unroll
            for (int q = 0; q < J / 4; ++q) {
                float4 w = w4[q * 172 + tid];   // global, L1-hit after step 0
                float4 va = v4[2 * q + 0];
                float4 vb = v4[2 * q + 1];
                a00 = fmaf(w.x, va.x, a00);
                a10 = fmaf(w.x, va.y, a10);
                a01 = fmaf(w.y, va.z, a01);
                a11 = fmaf(w.y, va.w, a11);
                a00 = fmaf(w.z, vb.x, a00);
                a10 = fmaf(w.z, vb.y, a10);
                a01 = fmaf(w.w, vb.z, a01);
                a11 = fmaf(w.w, vb.w, a11);
            }
            float z0 = a00 + a01;
            float z1 = a10 + a11;
            bool isg = (tid >= 86) && (tid < 129);
            sG[2 * tid + 0] = isg ? ftanh_(z0) : fsig(z0);
            sG[2 * tid + 1] = isg ? ftanh_(z1) : fsig(z1);
        }
        __syncthreads();  // B: gates ready

        if (tid < 86) {
            int r = jmy;
            float iv = sG[2 * r + bbit];
            float fv = sG[2 * (43 + r) + bbit];
            float gv = sG[2 * (86 + r) + bbit];
            float ov = sG[2 * (129 + r) + bbit];
            c = fv * c + iv * gv;
            float h = ov * ftanh_(c);
            sV[2 * (HOFF + r) + bbit] = h;
            (bbit ? out1 : out0)[(size_t)t * 86 + r] = h;
        }
        rin = rnext;
    }
}

// ---------------- Dense head: 64 rows per block (35 KB smem) ----------------
__global__ __launch_bounds__(64) void dense_kernel(
    const float* __restrict__ wd1, const float* __restrict__ bd1,
    const float* __restrict__ wd2, const float* __restrict__ bd2,
    const float* __restrict__ wo, const float* __restrict__ bo,
    float* __restrict__ outp) {
    __shared__ __align__(16) float s_w1[30 * 86];
    __shared__ __align__(16) float s_w2[20 * 30];
    __shared__ float s_b1[30], s_b2[20], s_wo[20];
    __shared__ __align__(16) float s_y[64 * 86];

    int tid = threadIdx.x;
    for (int i = tid; i < 30 * 86; i += 64) s_w1[i] = wd1[i];
    for (int i = tid; i < 20 * 30; i += 64) s_w2[i] = wd2[i];
    if (tid < 30) s_b1[tid] = bd1[tid];
    if (tid < 20) { s_b2[tid] = bd2[tid]; s_wo[tid] = wo[tid]; }

    size_t base = (size_t)blockIdx.x * 64;
    for (int i = tid; i < (64 * 86) / 2; i += 64)
        ((float2*)s_y)[i] = ((const float2*)(g_y2 + base * 86))[i];
    __syncthreads();

    const float* v = s_y + tid * 86;
    float h1[30];
#pragma unroll
    for (int k = 0; k < 30; ++k) h1[k] = s_b1[k];
    for (int cc = 0; cc < 86; ++cc) {
        float vv = v[cc];
#pragma unroll
        for (int k = 0; k < 30; ++k) h1[k] = fmaf(s_w1[k * 86 + cc], vv, h1[k]);
    }
    float h2[20];
#pragma unroll
    for (int k = 0; k < 20; ++k) h2[k] = s_b2[k];
#pragma unroll
    for (int cc = 0; cc < 30; ++cc) {
        float vv = fmaxf(h1[cc], 0.f);
#pragma unroll
        for (int k = 0; k < 20; ++k) h2[k] = fmaf(s_w2[k * 30 + cc], vv, h2[k]);
    }
    float o = bo[0];
#pragma unroll
    for (int k = 0; k < 20; ++k) o = fmaf(s_wo[k], fmaxf(h2[k], 0.f), o);
    outp[base + tid] = o;
}

extern "C" void kernel_launch(void* const* d_in, const int* in_sizes, int n_in,
                              void* d_out, int out_size) {
    const float* x = (const float*)d_in[0];
    PrepArgs A;
    A.w_proj = (const float*)d_in[1];
    A.b_proj = (const float*)d_in[2];
    for (int g = 0; g < 4; ++g) {
        A.wih[g] = (const float*)d_in[3 + g * 4 + 0];
        A.whh[g] = (const float*)d_in[3 + g * 4 + 1];
        A.bih[g] = (const float*)d_in[3 + g * 4 + 2];
        A.bhh[g] = (const float*)d_in[3 + g * 4 + 3];
    }
    const float* wd1 = (const float*)d_in[19];
    const float* bd1 = (const float*)d_in[20];
    const float* wd2 = (const float*)d_in[21];
    const float* bd2 = (const float*)d_in[22];
    const float* wo  = (const float*)d_in[23];
    const float* bo  = (const float*)d_in[24];

    const int smem1 = (52 * 172 + 2 * 52 + 2 * 172) * (int)sizeof(float);

    prep_kernel<<<64, 256>>>(A);
    lstm1_kernel<<<256, 192, smem1>>>(x);
    lstm2_kernel<<<256, 192>>>();
    dense_kernel<<<(BB * TT) / 64, 64>>>(wd1, bd1, wd2, bd2, wo, bo, (float*)d_out);
}